// round 3
// baseline (speedup 1.0000x reference)
#include <cuda_runtime.h>
#include <math.h>

#define KK 769      // 2M+1 states
#define MM 384      // latent length
#define BB 64
#define LL 256
#define AA 21
#define NEGV (-1.0e32f)

// ---------------- device scratch ----------------
__device__ float g_eobs[(AA + 1) * KK]; // exp(normalized emission logits), row AA = ones (missing)
__device__ float g_cm[KK];              // exp(direct-to-match-target - lse_row)
__device__ float g_ci[KK];              // exp(direct-to-insert-target - lse_row)
__device__ float g_cf[KK];              // exp(src_stay+src_del - lse_row) (chain source weight)
__device__ float g_et[KK];              // exp(t_term[kp]) (chain target weight)
__device__ float g_w[MM];               // w[j] = exp(d2[j]) (chain decay)
__device__ float g_einit[KK];           // exp(normalized initial log-probs)

// ---------------- prep: arrange + normalize all HMM constants ----------------
__global__ __launch_bounds__(512) void prep_kernel(
    const float* __restrict__ pre,   // (384,21)
    const float* __restrict__ iseq,  // (385,21)
    const float* __restrict__ ins,   // (384,3,2)
    const float* __restrict__ del)   // (384,3,2)
{
    __shared__ float lre[(MM + 1) * 3 * 2];
    __shared__ float lue[(MM + 1) * 3 * 2];
    __shared__ float sC[MM + 2];
    __shared__ float sW2[MM + 1];
    __shared__ float sQt[MM + 1];
    __shared__ float sG[MM + 1];
    __shared__ float WT[16], ST[16], FIN[16];
    __shared__ float sInit[KK];
    __shared__ float red[16];

    const int tid = threadIdx.x, lane = tid & 31, wid = tid >> 5;

    // 1. log-softmax of insert/delete (size-2 last dim) + boundary rows (r_M=1, u_M=0)
    for (int idx = tid; idx < MM * 3; idx += 512) {
        float x0 = ins[idx * 2], x1 = ins[idx * 2 + 1];
        float mx = fmaxf(x0, x1);
        float l = mx + __logf(__expf(x0 - mx) + __expf(x1 - mx));
        lre[idx * 2] = x0 - l; lre[idx * 2 + 1] = x1 - l;
        x0 = del[idx * 2]; x1 = del[idx * 2 + 1];
        mx = fmaxf(x0, x1);
        l = mx + __logf(__expf(x0 - mx) + __expf(x1 - mx));
        lue[idx * 2] = x0 - l; lue[idx * 2 + 1] = x1 - l;
    }
    if (tid < 3) {
        lre[(MM * 3 + tid) * 2 + 0] = NEGV; lre[(MM * 3 + tid) * 2 + 1] = 0.f;
        lue[(MM * 3 + tid) * 2 + 0] = 0.f;  lue[(MM * 3 + tid) * 2 + 1] = NEGV;
    }
    __syncthreads();

    // 2. C = exclusive cumsum of d2 ; w2, Qt
    {
        float d2 = 0.f;
        if (tid < MM) d2 = lre[(tid * 3 + 2) * 2 + 0] + lue[(tid * 3 + 2) * 2 + 1];
        float inc = d2;
        #pragma unroll
        for (int o = 1; o < 32; o <<= 1) {
            float t = __shfl_up_sync(0xffffffffu, inc, o);
            if (lane >= o) inc += t;
        }
        if (lane == 31) WT[wid] = inc;
        __syncthreads();
        float off = 0.f;
        for (int j = 0; j < wid; j++) off += WT[j];
        if (tid < MM) { sC[tid + 1] = inc + off; sW2[tid] = __expf(d2); }
        if (tid == 0) { sC[0] = 0.f; sC[MM + 1] = 0.f; sW2[MM] = 0.f; }
        if (tid <= MM) {
            float ti = lre[(tid * 3 + 2) * 2 + 1];
            float q = __expf(ti);
            if (tid < MM) q += __expf(lre[(tid * 3 + 2) * 2 + 0] + lue[(tid * 3 + 2) * 2 + 0]);
            sQt[tid] = q;
        }
        __syncthreads();
    }

    // 3. G via reverse affine scan
    {
        float A = 1.f, Bv = 0.f;
        if (tid < MM) { A = sW2[MM - tid]; Bv = sQt[MM - tid]; }
        #pragma unroll
        for (int o = 1; o < 32; o <<= 1) {
            float Wp = __shfl_up_sync(0xffffffffu, A, o);
            float Sp = __shfl_up_sync(0xffffffffu, Bv, o);
            if (lane >= o) { Bv = fmaf(A, Sp, Bv); A *= Wp; }
        }
        if (lane == 31 && wid < 12) { WT[wid] = A; ST[wid] = Bv; }
        __syncthreads();
        if (wid == 0) {
            float Wt = (lane < 12) ? WT[lane] : 1.f;
            float St = (lane < 12) ? ST[lane] : 0.f;
            #pragma unroll
            for (int o = 1; o < 16; o <<= 1) {
                float Wp = __shfl_up_sync(0xffffffffu, Wt, o);
                float Sp = __shfl_up_sync(0xffffffffu, St, o);
                if (lane >= o) { St = fmaf(Wt, Sp, St); Wt *= Wp; }
            }
            float e = __shfl_up_sync(0xffffffffu, St, 1);
            if (lane == 0) e = 0.f;
            if (lane < 12) FIN[lane] = e;
        }
        __syncthreads();
        if (tid < MM) sG[MM - 1 - tid] = fmaf(A, FIN[wid], Bv);
        if (tid == 0) sG[MM] = 0.f;
        __syncthreads();
    }

    // 4. per-state constants with analytic row logsumexp (scale-free)
    for (int k = tid; k < KK; k += 512) {
        const int m = (k < MM) ? k : k - MM;
        const int g = (k < MM) ? 0 : 1;
        const int s = m + 1 - g;
        float src_stay  = lre[(s * 3 + g) * 2 + 0];
        float src_ins   = lre[(s * 3 + g) * 2 + 1];
        float src_match = lue[(s * 3 + g) * 2 + 0];
        float src_del   = lue[(s * 3 + g) * 2 + 1];
        float dmatch = src_stay + src_match;
        float dins = src_ins;
        float cflog = src_stay + src_del;
        float rowsum = __expf(dins) + ((s < MM) ? __expf(dmatch) : 0.f) + __expf(cflog) * sG[s];
        float lse = __logf(rowsum);
        g_cm[k] = __expf(dmatch - lse);
        g_ci[k] = __expf(dins - lse);
        g_cf[k] = __expf(cflog - lse);
        float tterm = (g == 1) ? lre[(m * 3 + 2) * 2 + 1]
                               : (lre[(m * 3 + 2) * 2 + 0] + lue[(m * 3 + 2) * 2 + 0]);
        g_et[k] = __expf(tterm);
        float initv;
        if (m == 0) initv = (g == 1) ? lre[1] : (lre[0] + lue[0]);
        else        initv = lre[0] + lue[1] - sC[1] + sC[m] + tterm;
        sInit[k] = initv;
    }
    if (tid < MM) g_w[tid] = sW2[tid];
    __syncthreads();

    // 5. normalized exp(init)
    {
        float mloc = -INFINITY;
        for (int k = tid; k < KK; k += 512) mloc = fmaxf(mloc, sInit[k]);
        #pragma unroll
        for (int o = 16; o; o >>= 1) mloc = fmaxf(mloc, __shfl_xor_sync(0xffffffffu, mloc, o));
        if (lane == 0) red[wid] = mloc;
        __syncthreads();
        float mxI = red[0];
        #pragma unroll
        for (int j = 1; j < 16; j++) mxI = fmaxf(mxI, red[j]);
        __syncthreads();
        float s0 = 0.f;
        for (int k = tid; k < KK; k += 512) s0 += __expf(sInit[k] - mxI);
        #pragma unroll
        for (int o = 16; o; o >>= 1) s0 += __shfl_xor_sync(0xffffffffu, s0, o);
        if (lane == 0) red[wid] = s0;
        __syncthreads();
        float Z = 0.f;
        for (int j = 0; j < 16; j++) Z += red[j];
        float lz = mxI + __logf(Z);
        for (int k = tid; k < KK; k += 512) g_einit[k] = __expf(sInit[k] - lz);
    }

    // 6. emission probs, double-normalized over A, pre-exponentiated, transposed; row AA = ones
    for (int k = tid; k < KK; k += 512) {
        const float* row = (k < MM) ? (pre + k * AA) : (iseq + (k - MM) * AA);
        float mx = -INFINITY;
        for (int a = 0; a < AA; a++) mx = fmaxf(mx, row[a]);
        float sm = 0.f;
        for (int a = 0; a < AA; a++) sm += __expf(row[a] - mx);
        float l = mx + __logf(sm);
        float sm2 = 0.f;
        for (int a = 0; a < AA; a++) sm2 += __expf(row[a] - l);
        float l2 = __logf(sm2);
        for (int a = 0; a < AA; a++) g_eobs[a * KK + k] = __expf((row[a] - l) - l2);
        g_eobs[AA * KK + k] = 1.0f;
    }
}

// ---------------- forward recursion (normalized linear domain), one CTA per batch ----------------
__global__ __launch_bounds__(512) void hmm_forward(const float* __restrict__ seq,
                                                   const float* __restrict__ lscale,
                                                   float* __restrict__ out)
{
    __shared__ float s_ea[2][KK];          // ping-pong scaled-linear alpha
    __shared__ float s_Ws[MM], s_Ss[MM];   // inclusive affine scan state
    __shared__ float s_WT[12], s_ST[12];   // warp totals
    __shared__ float s_Z[16];              // warp partial sums of u
    __shared__ int   s_let[LL];

    const int b = blockIdx.x, tid = threadIdx.x, lane = tid & 31, wid = tid >> 5;
    const bool has2 = tid < (KK - 512);    // tid < 257 owns second state 512+tid

    // letters for this batch (row index into g_eobs; AA = missing)
    for (int l = tid; l < LL; l += 512) {
        const float* row = seq + ((size_t)b * LL + l) * AA;
        int let = AA;
        #pragma unroll
        for (int a = 0; a < AA; a++)
            if (row[a] > 0.5f) let = a;
        s_let[l] = let;
    }

    // loop-invariant per-thread constants
    const bool scn = tid < MM;
    const float wv_c = scn ? g_w[tid] : 1.f;
    const float cf_a = scn ? g_cf[MM + tid] : 0.f;
    const float cf_b = (scn && tid >= 1) ? g_cf[tid - 1] : 0.f;

    const bool insd1 = tid >= MM;
    const int m1 = insd1 ? tid - MM : tid;
    const float et1 = g_et[tid];
    const float ca1 = insd1 ? g_ci[MM + m1] : g_cm[MM + m1];
    const float cb1 = (m1 >= 1) ? (insd1 ? g_ci[m1 - 1] : g_cm[m1 - 1]) : 0.f;
    const int jb1 = (m1 >= 1) ? m1 - 1 : 0;
    const int idx1 = jb1 >> 5;

    const int m2 = tid + 128;              // kp2 = 512+tid = MM+m2 (insert), valid if has2
    const float et2 = has2 ? g_et[512 + tid] : 0.f;
    const float ca2 = has2 ? g_ci[MM + m2] : 0.f;
    const float cb2 = has2 ? g_ci[m2 - 1] : 0.f;
    const int idx2 = (m2 - 1) >> 5;

    __syncthreads();

    // init u0 = exp(init) * emission
    int cur = 0;
    {
        const float* ob = g_eobs + s_let[0] * KK;
        s_ea[0][tid] = g_einit[tid] * ob[tid];
        if (has2) s_ea[0][512 + tid] = g_einit[512 + tid] * ob[512 + tid];
    }
    __syncthreads();

    float Lacc = 0.f;

    for (int t = 1; t < LL; t++) {
        const float* u = s_ea[cur];
        const float* ob = g_eobs + s_let[t] * KK;   // prefetch emission row
        const float e1 = ob[tid];
        const float e2 = has2 ? ob[512 + tid] : 0.f;

        // ---- phase 1: affine scan of chain sources + Z partial sums (warps 0-11) ----
        if (scn) {
            float ua = u[MM + tid];
            float ub = (tid >= 1) ? u[tid - 1] : 0.f;
            float Sv = ua * cf_a + ub * cf_b;
            float zs = ua + ub;
            if (tid == 0) zs += u[MM - 1] + u[KK - 1];   // the two states not covered
            float Wv = wv_c;
            #pragma unroll
            for (int o = 1; o < 32; o <<= 1) {
                float Wp = __shfl_up_sync(0xffffffffu, Wv, o);
                float Sp = __shfl_up_sync(0xffffffffu, Sv, o);
                if (lane >= o) { Sv = fmaf(Wv, Sp, Sv); Wv *= Wp; }
            }
            #pragma unroll
            for (int o = 16; o; o >>= 1) zs += __shfl_xor_sync(0xffffffffu, zs, o);
            s_Ws[tid] = Wv; s_Ss[tid] = Sv;
            if (lane == 31) { s_WT[wid] = Wv; s_ST[wid] = Sv; }
            if (lane == 0) s_Z[wid] = zs;
        }
        __syncthreads();

        // ---- phase 2: per-target combine + normalize + emission ----
        float Z = 0.f;
        #pragma unroll
        for (int j = 0; j < 12; j++) Z += s_Z[j];
        const float rz = __fdividef(1.f, Z);
        Lacc += __logf(Z);

        // compose warp totals up to each needed warp index (redundant serial chain)
        float F1 = 0.f, F2 = 0.f;
        #pragma unroll
        for (int jj = 0; jj < 11; jj++) {
            float Wt = s_WT[jj], St = s_ST[jj];
            if (jj < idx1) F1 = fmaf(Wt, F1, St);
            if (jj < idx2) F2 = fmaf(Wt, F2, St);
        }
        float fm1 = (m1 >= 1) ? fmaf(s_Ws[jb1], F1, s_Ss[jb1]) : 0.f;
        float pr1 = et1 * fm1;
        pr1 = fmaf(u[MM + m1], ca1, pr1);
        pr1 = fmaf(u[jb1], cb1, pr1);
        const float un1 = pr1 * e1 * rz;

        float un2 = 0.f;
        if (has2) {
            const int j2 = m2 - 1;
            float fm2 = fmaf(s_Ws[j2], F2, s_Ss[j2]);
            float pr2 = et2 * fm2;
            pr2 = fmaf(u[MM + m2], ca2, pr2);
            pr2 = fmaf(u[j2], cb2, pr2);
            un2 = pr2 * e2 * rz;
        }
        float* un = s_ea[cur ^ 1];
        un[tid] = un1;
        if (has2) un[512 + tid] = un2;
        __syncthreads();
        cur ^= 1;
    }

    // ---- final: log(sum u) + accumulated log-scale ----
    const float* u = s_ea[cur];
    float ps = u[tid] + (has2 ? u[512 + tid] : 0.f);
    #pragma unroll
    for (int o = 16; o; o >>= 1) ps += __shfl_xor_sync(0xffffffffu, ps, o);
    if (lane == 0) s_Z[wid] = ps;
    __syncthreads();
    if (tid == 0) {
        float Zt = 0.f;
        for (int j = 0; j < 16; j++) Zt += s_Z[j];
        out[b] = lscale[0] * (Lacc + __logf(Zt));
    }
}

extern "C" void kernel_launch(void* const* d_in, const int* in_sizes, int n_in,
                              void* d_out, int out_size)
{
    const float* pre  = (const float*)d_in[0];   // precursor_seq (384,21)
    const float* iseq = (const float*)d_in[1];   // insert_seq (385,21)
    const float* ins  = (const float*)d_in[2];   // insert (384,3,2)
    const float* del  = (const float*)d_in[3];   // delete (384,3,2)
    const float* seq  = (const float*)d_in[4];   // seq_data (64,256,21)
    const float* ls   = (const float*)d_in[5];   // local_scale (1,)
    float* out = (float*)d_out;                  // (64,)

    prep_kernel<<<1, 512>>>(pre, iseq, ins, del);
    hmm_forward<<<BB, 512>>>(seq, ls, out);
}

// round 4
// speedup vs baseline: 4.6524x; 4.6524x over previous
#include <cuda_runtime.h>
#include <math.h>

#define KK 769      // 2M+1 states
#define MM 384      // latent length
#define BB 64
#define LL 256
#define AA 21
#define NEGV (-1.0e32f)

// ---------------- device scratch ----------------
__device__ float g_eobs[(AA + 1) * KK]; // exp(normalized emission logits), row AA = ones (missing)
__device__ float g_cm[KK];              // exp(direct-to-match-target - lse_row)
__device__ float g_ci[KK];              // exp(direct-to-insert-target - lse_row)
__device__ float g_cf[KK];              // exp(src_stay+src_del - lse_row) (chain source weight)
__device__ float g_et[KK];              // exp(t_term[kp]) (chain target weight)
__device__ float g_w[MM];               // w[j] = exp(d2[j]) (chain decay)
__device__ float g_einit[KK];           // exp(normalized initial log-probs)

// ---------------- prep: arrange + normalize all HMM constants ----------------
__global__ __launch_bounds__(512) void prep_kernel(
    const float* __restrict__ pre,   // (384,21)
    const float* __restrict__ iseq,  // (385,21)
    const float* __restrict__ ins,   // (384,3,2)
    const float* __restrict__ del)   // (384,3,2)
{
    __shared__ float lre[(MM + 1) * 3 * 2];
    __shared__ float lue[(MM + 1) * 3 * 2];
    __shared__ float sC[MM + 2];
    __shared__ float sW2[MM + 1];
    __shared__ float sQt[MM + 1];
    __shared__ float sG[MM + 1];
    __shared__ float WT[16], ST[16], FIN[16];
    __shared__ float sInit[KK];
    __shared__ float sNorm[KK];
    __shared__ float red[16];

    const int tid = threadIdx.x, lane = tid & 31, wid = tid >> 5;

    // 1. log-softmax of insert/delete (size-2 last dim) + boundary rows (r_M=1, u_M=0)
    for (int idx = tid; idx < MM * 3; idx += 512) {
        float x0 = ins[idx * 2], x1 = ins[idx * 2 + 1];
        float mx = fmaxf(x0, x1);
        float l = mx + __logf(__expf(x0 - mx) + __expf(x1 - mx));
        lre[idx * 2] = x0 - l; lre[idx * 2 + 1] = x1 - l;
        x0 = del[idx * 2]; x1 = del[idx * 2 + 1];
        mx = fmaxf(x0, x1);
        l = mx + __logf(__expf(x0 - mx) + __expf(x1 - mx));
        lue[idx * 2] = x0 - l; lue[idx * 2 + 1] = x1 - l;
    }
    if (tid < 3) {
        lre[(MM * 3 + tid) * 2 + 0] = NEGV; lre[(MM * 3 + tid) * 2 + 1] = 0.f;
        lue[(MM * 3 + tid) * 2 + 0] = 0.f;  lue[(MM * 3 + tid) * 2 + 1] = NEGV;
    }
    __syncthreads();

    // 2. C = exclusive cumsum of d2 ; w2, Qt
    {
        float d2 = 0.f;
        if (tid < MM) d2 = lre[(tid * 3 + 2) * 2 + 0] + lue[(tid * 3 + 2) * 2 + 1];
        float inc = d2;
        #pragma unroll
        for (int o = 1; o < 32; o <<= 1) {
            float t = __shfl_up_sync(0xffffffffu, inc, o);
            if (lane >= o) inc += t;
        }
        if (lane == 31) WT[wid] = inc;
        __syncthreads();
        float off = 0.f;
        for (int j = 0; j < wid; j++) off += WT[j];
        if (tid < MM) { sC[tid + 1] = inc + off; sW2[tid] = __expf(d2); }
        if (tid == 0) { sC[0] = 0.f; sC[MM + 1] = 0.f; sW2[MM] = 0.f; }
        if (tid <= MM) {
            float ti = lre[(tid * 3 + 2) * 2 + 1];
            float q = __expf(ti);
            if (tid < MM) q += __expf(lre[(tid * 3 + 2) * 2 + 0] + lue[(tid * 3 + 2) * 2 + 0]);
            sQt[tid] = q;
        }
        __syncthreads();
    }

    // 3. G via reverse affine scan
    {
        float A = 1.f, Bv = 0.f;
        if (tid < MM) { A = sW2[MM - tid]; Bv = sQt[MM - tid]; }
        #pragma unroll
        for (int o = 1; o < 32; o <<= 1) {
            float Wp = __shfl_up_sync(0xffffffffu, A, o);
            float Sp = __shfl_up_sync(0xffffffffu, Bv, o);
            if (lane >= o) { Bv = fmaf(A, Sp, Bv); A *= Wp; }
        }
        if (lane == 31 && wid < 12) { WT[wid] = A; ST[wid] = Bv; }
        __syncthreads();
        if (wid == 0) {
            float Wt = (lane < 12) ? WT[lane] : 1.f;
            float St = (lane < 12) ? ST[lane] : 0.f;
            #pragma unroll
            for (int o = 1; o < 16; o <<= 1) {
                float Wp = __shfl_up_sync(0xffffffffu, Wt, o);
                float Sp = __shfl_up_sync(0xffffffffu, St, o);
                if (lane >= o) { St = fmaf(Wt, Sp, St); Wt *= Wp; }
            }
            float e = __shfl_up_sync(0xffffffffu, St, 1);
            if (lane == 0) e = 0.f;
            if (lane < 12) FIN[lane] = e;
        }
        __syncthreads();
        if (tid < MM) sG[MM - 1 - tid] = fmaf(A, FIN[wid], Bv);
        if (tid == 0) sG[MM] = 0.f;
        __syncthreads();
    }

    // 4. per-state constants with analytic row logsumexp (scale-free)
    for (int k = tid; k < KK; k += 512) {
        const int m = (k < MM) ? k : k - MM;
        const int g = (k < MM) ? 0 : 1;
        const int s = m + 1 - g;
        float src_stay  = lre[(s * 3 + g) * 2 + 0];
        float src_ins   = lre[(s * 3 + g) * 2 + 1];
        float src_match = lue[(s * 3 + g) * 2 + 0];
        float src_del   = lue[(s * 3 + g) * 2 + 1];
        float dmatch = src_stay + src_match;
        float dins = src_ins;
        float cflog = src_stay + src_del;
        float rowsum = __expf(dins) + ((s < MM) ? __expf(dmatch) : 0.f) + __expf(cflog) * sG[s];
        float lse = __logf(rowsum);
        g_cm[k] = __expf(dmatch - lse);
        g_ci[k] = __expf(dins - lse);
        g_cf[k] = __expf(cflog - lse);
        float tterm = (g == 1) ? lre[(m * 3 + 2) * 2 + 1]
                               : (lre[(m * 3 + 2) * 2 + 0] + lue[(m * 3 + 2) * 2 + 0]);
        g_et[k] = __expf(tterm);
        float initv;
        if (m == 0) initv = (g == 1) ? lre[1] : (lre[0] + lue[0]);
        else        initv = lre[0] + lue[1] - sC[1] + sC[m] + tterm;
        sInit[k] = initv;
    }
    if (tid < MM) g_w[tid] = sW2[tid];
    __syncthreads();

    // 5. normalized exp(init)
    {
        float mloc = -INFINITY;
        for (int k = tid; k < KK; k += 512) mloc = fmaxf(mloc, sInit[k]);
        #pragma unroll
        for (int o = 16; o; o >>= 1) mloc = fmaxf(mloc, __shfl_xor_sync(0xffffffffu, mloc, o));
        if (lane == 0) red[wid] = mloc;
        __syncthreads();
        float mxI = red[0];
        #pragma unroll
        for (int j = 1; j < 16; j++) mxI = fmaxf(mxI, red[j]);
        __syncthreads();
        float s0 = 0.f;
        for (int k = tid; k < KK; k += 512) s0 += __expf(sInit[k] - mxI);
        #pragma unroll
        for (int o = 16; o; o >>= 1) s0 += __shfl_xor_sync(0xffffffffu, s0, o);
        if (lane == 0) red[wid] = s0;
        __syncthreads();
        float Z = 0.f;
        for (int j = 0; j < 16; j++) Z += red[j];
        float lz = mxI + __logf(Z);
        for (int k = tid; k < KK; k += 512) g_einit[k] = __expf(sInit[k] - lz);
    }

    // 6a. emission normalizers per state
    for (int k = tid; k < KK; k += 512) {
        const float* row = (k < MM) ? (pre + k * AA) : (iseq + (k - MM) * AA);
        float mx = -INFINITY;
        for (int a = 0; a < AA; a++) mx = fmaxf(mx, row[a]);
        float sm = 0.f;
        for (int a = 0; a < AA; a++) sm += __expf(row[a] - mx);
        float l = mx + __logf(sm);
        float sm2 = 0.f;
        for (int a = 0; a < AA; a++) sm2 += __expf(row[a] - l);
        sNorm[k] = l + __logf(sm2);
    }
    __syncthreads();
    // 6b. coalesced transposed store of exp(emission)
    for (int i = tid; i < (AA + 1) * KK; i += 512) {
        int a = i / KK;
        int k = i - a * KK;
        float v;
        if (a == AA) v = 1.0f;
        else {
            float x = (k < MM) ? pre[k * AA + a] : iseq[(k - MM) * AA + a];
            v = __expf(x - sNorm[k]);
        }
        g_eobs[i] = v;
    }
}

// ---------------- forward recursion (normalized linear domain), one CTA per batch ----------------
__global__ __launch_bounds__(384) void hmm_forward(const float* __restrict__ seq,
                                                   const float* __restrict__ lscale,
                                                   float* __restrict__ out)
{
    __shared__ float s_ea[2][KK];       // ping-pong scaled-linear alpha
    __shared__ float4 s_T[12];          // warp totals (W, S, z, -)
    __shared__ float s_red[12];
    __shared__ int   s_let[LL];

    const int b = blockIdx.x, tid = threadIdx.x, lane = tid & 31, wid = tid >> 5;
    const bool last = (tid == MM - 1);  // thread 383 also owns state k=768 (insert m=384)

    // letters for this batch
    for (int l = tid; l < LL; l += 384) {
        const float* row = seq + ((size_t)b * LL + l) * AA;
        int let = AA;
        #pragma unroll
        for (int a = 0; a < AA; a++)
            if (row[a] > 0.5f) let = a;
        s_let[l] = let;
    }

    // loop-invariant constants (thread m owns targets: match m, insert m)
    const float w_c  = g_w[tid];
    const float cf_a = g_cf[MM + tid];
    const float cf_b = tid ? g_cf[tid - 1] : 0.f;
    const float cm_a = g_cm[MM + tid];
    const float cm_b = tid ? g_cm[tid - 1] : 0.f;
    const float ci_a = g_ci[MM + tid];
    const float ci_b = tid ? g_ci[tid - 1] : 0.f;
    const float et_m = g_et[tid];
    const float et_i = g_et[MM + tid];
    float et_x = 0.f, ci_xa = 0.f, ci_xb = 0.f;
    if (last) { et_x = g_et[KK - 1]; ci_xa = g_ci[KK - 1]; ci_xb = g_ci[MM - 1]; }
    __syncthreads();

    // init: u0 = exp(init) * emission(t=0)
    int cur = 0;
    {
        const float* ob = g_eobs + s_let[0] * KK;
        s_ea[0][tid]      = g_einit[tid]      * ob[tid];
        s_ea[0][MM + tid] = g_einit[MM + tid] * ob[MM + tid];
        if (last) s_ea[0][KK - 1] = g_einit[KK - 1] * ob[KK - 1];
    }
    __syncthreads();

    int pacc = 0;

    for (int t = 1; t < LL; t++) {
        const float* u = s_ea[cur];
        const float* ob = g_eobs + s_let[t] * KK;   // emission prefetch (L1-resident)
        const float e_m = ob[tid];
        const float e_i = ob[MM + tid];
        float e_x = 0.f, u_x = 0.f, u_p = 0.f;
        if (last) { e_x = ob[KK - 1]; u_x = u[KK - 1]; u_p = u[MM - 1]; }

        // ---- phase 1: sources + affine scan + z partial (all registers/shuffles) ----
        const float u_a = u[MM + tid];
        const float u_b = tid ? u[tid - 1] : 0.f;
        float zs = u_a + u_b;
        if (tid == 0) zs += u[MM - 1] + u[KK - 1];
        float Wv = w_c, Sv = fmaf(u_b, cf_b, u_a * cf_a);
        #pragma unroll
        for (int o = 1; o < 32; o <<= 1) {
            float Wp = __shfl_up_sync(0xffffffffu, Wv, o);
            float Sp = __shfl_up_sync(0xffffffffu, Sv, o);
            if (lane >= o) { Sv = fmaf(Wv, Sp, Sv); Wv *= Wp; }
        }
        #pragma unroll
        for (int o = 16; o; o >>= 1) zs += __shfl_xor_sync(0xffffffffu, zs, o);
        if (lane == 31) s_T[wid] = make_float4(Wv, Sv, zs, 0.f);
        __syncthreads();

        // ---- phase 2: redundant per-warp totals scan (shuffles only) + combine ----
        float Tw = 1.f, Ts = 0.f, Tz = 0.f;
        if (lane < 12) { float4 T = s_T[lane]; Tw = T.x; Ts = T.y; Tz = T.z; }
        #pragma unroll
        for (int o = 1; o < 16; o <<= 1) {
            float Wp = __shfl_up_sync(0xffffffffu, Tw, o);
            float Sp = __shfl_up_sync(0xffffffffu, Ts, o);
            if (lane >= o) { Ts = fmaf(Tw, Sp, Ts); Tw *= Wp; }
        }
        #pragma unroll
        for (int o = 16; o; o >>= 1) Tz += __shfl_xor_sync(0xffffffffu, Tz, o);
        const int wm1 = (wid > 0) ? wid - 1 : 0;
        float FinW = __shfl_sync(0xffffffffu, Ts, wm1);   // incoming F for this warp
        if (wid == 0) FinW = 0.f;

        // power-of-two rescale from Z's exponent (exact, no MUFU)
        const unsigned ze = (__float_as_uint(Tz) >> 23) & 255u;
        pacc += (int)ze - 127;
        const float rz = __uint_as_float((254u - ze) << 23);

        // F[m] from neighbor's inclusive scan registers
        float Wp = __shfl_up_sync(0xffffffffu, Wv, 1);
        float Sp = __shfl_up_sync(0xffffffffu, Sv, 1);
        float fm = lane ? fmaf(Wp, FinW, Sp) : FinW;
        if (tid == 0) fm = 0.f;

        float pr_m = fmaf(u_b, cm_b, fmaf(u_a, cm_a, et_m * fm));
        float pr_i = fmaf(u_b, ci_b, fmaf(u_a, ci_a, et_i * fm));
        float* un = s_ea[cur ^ 1];
        un[tid]      = pr_m * e_m * rz;
        un[MM + tid] = pr_i * e_i * rz;
        if (last) {
            float fmx = fmaf(Wv, FinW, Sv);       // F[384] = global inclusive at 383
            float pr_x = fmaf(u_p, ci_xb, fmaf(u_x, ci_xa, et_x * fmx));
            un[KK - 1] = pr_x * e_x * rz;
        }
        __syncthreads();
        cur ^= 1;
    }

    // ---- final: log(sum u) + 2^pacc correction ----
    const float* u = s_ea[cur];
    float ps = u[tid] + u[MM + tid];
    if (last) ps += u[KK - 1];
    #pragma unroll
    for (int o = 16; o; o >>= 1) ps += __shfl_xor_sync(0xffffffffu, ps, o);
    if (lane == 0) s_red[wid] = ps;
    __syncthreads();
    if (tid == 0) {
        float Zt = 0.f;
        for (int j = 0; j < 12; j++) Zt += s_red[j];
        out[b] = lscale[0] * ((float)((double)pacc * 0.6931471805599453) + __logf(Zt));
    }
}

extern "C" void kernel_launch(void* const* d_in, const int* in_sizes, int n_in,
                              void* d_out, int out_size)
{
    const float* pre  = (const float*)d_in[0];   // precursor_seq (384,21)
    const float* iseq = (const float*)d_in[1];   // insert_seq (385,21)
    const float* ins  = (const float*)d_in[2];   // insert (384,3,2)
    const float* del  = (const float*)d_in[3];   // delete (384,3,2)
    const float* seq  = (const float*)d_in[4];   // seq_data (64,256,21)
    const float* ls   = (const float*)d_in[5];   // local_scale (1,)
    float* out = (float*)d_out;                  // (64,)

    prep_kernel<<<1, 512>>>(pre, iseq, ins, del);
    hmm_forward<<<BB, 384>>>(seq, ls, out);
}

// round 5
// speedup vs baseline: 6.2141x; 1.3357x over previous
#include <cuda_runtime.h>
#include <math.h>

#define KK 769      // 2M+1 states
#define MM 384      // latent length
#define BB 64
#define LL 256
#define AA 21
#define NEGV (-1.0e32f)

// ---------------- device scratch ----------------
__device__ float g_eobs[(AA + 1) * KK]; // exp(normalized emission logits), row AA = ones (missing)
__device__ float g_cm[KK];              // exp(direct-to-match-target - lse_row)
__device__ float g_ci[KK];              // exp(direct-to-insert-target - lse_row)
__device__ float g_cf[KK];              // exp(src_stay+src_del - lse_row) (chain source weight)
__device__ float g_et[KK];              // exp(t_term[kp]) (chain target weight)
__device__ float g_w[MM];               // w[j] = exp(d2[j]) (chain decay)
__device__ float g_einit[KK];           // exp(normalized initial log-probs)

// ---------------- prep: arrange + normalize all HMM constants ----------------
__global__ __launch_bounds__(512) void prep_kernel(
    const float* __restrict__ pre,   // (384,21)
    const float* __restrict__ iseq,  // (385,21)
    const float* __restrict__ ins,   // (384,3,2)
    const float* __restrict__ del)   // (384,3,2)
{
    __shared__ float lre[(MM + 1) * 3 * 2];
    __shared__ float lue[(MM + 1) * 3 * 2];
    __shared__ float sC[MM + 2];
    __shared__ float sW2[MM + 1];
    __shared__ float sQt[MM + 1];
    __shared__ float sG[MM + 1];
    __shared__ float WT[16], ST[16], FIN[16];
    __shared__ float sInit[KK];
    __shared__ float sNorm[KK];
    __shared__ float red[16];

    const int tid = threadIdx.x, lane = tid & 31, wid = tid >> 5;

    // 1. log-softmax of insert/delete (size-2 last dim) + boundary rows (r_M=1, u_M=0)
    for (int idx = tid; idx < MM * 3; idx += 512) {
        float x0 = ins[idx * 2], x1 = ins[idx * 2 + 1];
        float mx = fmaxf(x0, x1);
        float l = mx + __logf(__expf(x0 - mx) + __expf(x1 - mx));
        lre[idx * 2] = x0 - l; lre[idx * 2 + 1] = x1 - l;
        x0 = del[idx * 2]; x1 = del[idx * 2 + 1];
        mx = fmaxf(x0, x1);
        l = mx + __logf(__expf(x0 - mx) + __expf(x1 - mx));
        lue[idx * 2] = x0 - l; lue[idx * 2 + 1] = x1 - l;
    }
    if (tid < 3) {
        lre[(MM * 3 + tid) * 2 + 0] = NEGV; lre[(MM * 3 + tid) * 2 + 1] = 0.f;
        lue[(MM * 3 + tid) * 2 + 0] = 0.f;  lue[(MM * 3 + tid) * 2 + 1] = NEGV;
    }
    __syncthreads();

    // 2. C = exclusive cumsum of d2 ; w2, Qt
    {
        float d2 = 0.f;
        if (tid < MM) d2 = lre[(tid * 3 + 2) * 2 + 0] + lue[(tid * 3 + 2) * 2 + 1];
        float inc = d2;
        #pragma unroll
        for (int o = 1; o < 32; o <<= 1) {
            float t = __shfl_up_sync(0xffffffffu, inc, o);
            if (lane >= o) inc += t;
        }
        if (lane == 31) WT[wid] = inc;
        __syncthreads();
        float off = 0.f;
        for (int j = 0; j < wid; j++) off += WT[j];
        if (tid < MM) { sC[tid + 1] = inc + off; sW2[tid] = __expf(d2); }
        if (tid == 0) { sC[0] = 0.f; sC[MM + 1] = 0.f; sW2[MM] = 0.f; }
        if (tid <= MM) {
            float ti = lre[(tid * 3 + 2) * 2 + 1];
            float q = __expf(ti);
            if (tid < MM) q += __expf(lre[(tid * 3 + 2) * 2 + 0] + lue[(tid * 3 + 2) * 2 + 0]);
            sQt[tid] = q;
        }
        __syncthreads();
    }

    // 3. G via reverse affine scan
    {
        float A = 1.f, Bv = 0.f;
        if (tid < MM) { A = sW2[MM - tid]; Bv = sQt[MM - tid]; }
        #pragma unroll
        for (int o = 1; o < 32; o <<= 1) {
            float Wp = __shfl_up_sync(0xffffffffu, A, o);
            float Sp = __shfl_up_sync(0xffffffffu, Bv, o);
            if (lane >= o) { Bv = fmaf(A, Sp, Bv); A *= Wp; }
        }
        if (lane == 31 && wid < 12) { WT[wid] = A; ST[wid] = Bv; }
        __syncthreads();
        if (wid == 0) {
            float Wt = (lane < 12) ? WT[lane] : 1.f;
            float St = (lane < 12) ? ST[lane] : 0.f;
            #pragma unroll
            for (int o = 1; o < 16; o <<= 1) {
                float Wp = __shfl_up_sync(0xffffffffu, Wt, o);
                float Sp = __shfl_up_sync(0xffffffffu, St, o);
                if (lane >= o) { St = fmaf(Wt, Sp, St); Wt *= Wp; }
            }
            float e = __shfl_up_sync(0xffffffffu, St, 1);
            if (lane == 0) e = 0.f;
            if (lane < 12) FIN[lane] = e;
        }
        __syncthreads();
        if (tid < MM) sG[MM - 1 - tid] = fmaf(A, FIN[wid], Bv);
        if (tid == 0) sG[MM] = 0.f;
        __syncthreads();
    }

    // 4. per-state constants with analytic row logsumexp (scale-free)
    for (int k = tid; k < KK; k += 512) {
        const int m = (k < MM) ? k : k - MM;
        const int g = (k < MM) ? 0 : 1;
        const int s = m + 1 - g;
        float src_stay  = lre[(s * 3 + g) * 2 + 0];
        float src_ins   = lre[(s * 3 + g) * 2 + 1];
        float src_match = lue[(s * 3 + g) * 2 + 0];
        float src_del   = lue[(s * 3 + g) * 2 + 1];
        float dmatch = src_stay + src_match;
        float dins = src_ins;
        float cflog = src_stay + src_del;
        float rowsum = __expf(dins) + ((s < MM) ? __expf(dmatch) : 0.f) + __expf(cflog) * sG[s];
        float lse = __logf(rowsum);
        g_cm[k] = __expf(dmatch - lse);
        g_ci[k] = __expf(dins - lse);
        g_cf[k] = __expf(cflog - lse);
        float tterm = (g == 1) ? lre[(m * 3 + 2) * 2 + 1]
                               : (lre[(m * 3 + 2) * 2 + 0] + lue[(m * 3 + 2) * 2 + 0]);
        g_et[k] = __expf(tterm);
        float initv;
        if (m == 0) initv = (g == 1) ? lre[1] : (lre[0] + lue[0]);
        else        initv = lre[0] + lue[1] - sC[1] + sC[m] + tterm;
        sInit[k] = initv;
    }
    if (tid < MM) g_w[tid] = sW2[tid];
    __syncthreads();

    // 5. normalized exp(init)
    {
        float mloc = -INFINITY;
        for (int k = tid; k < KK; k += 512) mloc = fmaxf(mloc, sInit[k]);
        #pragma unroll
        for (int o = 16; o; o >>= 1) mloc = fmaxf(mloc, __shfl_xor_sync(0xffffffffu, mloc, o));
        if (lane == 0) red[wid] = mloc;
        __syncthreads();
        float mxI = red[0];
        #pragma unroll
        for (int j = 1; j < 16; j++) mxI = fmaxf(mxI, red[j]);
        __syncthreads();
        float s0 = 0.f;
        for (int k = tid; k < KK; k += 512) s0 += __expf(sInit[k] - mxI);
        #pragma unroll
        for (int o = 16; o; o >>= 1) s0 += __shfl_xor_sync(0xffffffffu, s0, o);
        if (lane == 0) red[wid] = s0;
        __syncthreads();
        float Z = 0.f;
        for (int j = 0; j < 16; j++) Z += red[j];
        float lz = mxI + __logf(Z);
        for (int k = tid; k < KK; k += 512) g_einit[k] = __expf(sInit[k] - lz);
    }

    // 6a. emission normalizers per state
    for (int k = tid; k < KK; k += 512) {
        const float* row = (k < MM) ? (pre + k * AA) : (iseq + (k - MM) * AA);
        float mx = -INFINITY;
        for (int a = 0; a < AA; a++) mx = fmaxf(mx, row[a]);
        float sm = 0.f;
        for (int a = 0; a < AA; a++) sm += __expf(row[a] - mx);
        float l = mx + __logf(sm);
        float sm2 = 0.f;
        for (int a = 0; a < AA; a++) sm2 += __expf(row[a] - l);
        sNorm[k] = l + __logf(sm2);
    }
    __syncthreads();
    // 6b. coalesced transposed store of exp(emission)
    for (int i = tid; i < (AA + 1) * KK; i += 512) {
        int a = i / KK;
        int k = i - a * KK;
        float v;
        if (a == AA) v = 1.0f;
        else {
            float x = (k < MM) ? pre[k * AA + a] : iseq[(k - MM) * AA + a];
            v = __expf(x - sNorm[k]);
        }
        g_eobs[i] = v;
    }
}

// ---------------- forward recursion: 128 threads, 3 chain elements / 6 states per thread ----------------
__global__ __launch_bounds__(128) void hmm_forward(const float* __restrict__ seq,
                                                   const float* __restrict__ lscale,
                                                   float* __restrict__ out)
{
    __shared__ float s_ea[2][KK];       // ping-pong scaled-linear alpha
    __shared__ float4 s_T[4];           // warp totals (W, S, z, -)
    __shared__ float s_red[4];
    __shared__ int   s_let[LL];

    const int b = blockIdx.x, tid = threadIdx.x, lane = tid & 31, wid = tid >> 5;
    const int j0 = tid * 3;             // first owned chain element / m-position
    const bool lastT = (tid == 127);    // also owns insert m=384 (k=768)

    // letters for this batch
    for (int l = tid; l < LL; l += 128) {
        const float* row = seq + ((size_t)b * LL + l) * AA;
        int let = AA;
        #pragma unroll
        for (int a = 0; a < AA; a++)
            if (row[a] > 0.5f) let = a;
        s_let[l] = let;
    }

    // loop-invariant constants, 3 elements per thread
    float w_[3], cfa[3], cfb[3], cma[3], cmb[3], cia[3], cib[3], etm[3], eti[3];
    #pragma unroll
    for (int q = 0; q < 3; q++) {
        const int j = j0 + q;
        w_[q]  = g_w[j];
        cfa[q] = g_cf[MM + j];  cfb[q] = j ? g_cf[j - 1] : 0.f;
        cma[q] = g_cm[MM + j];  cmb[q] = j ? g_cm[j - 1] : 0.f;
        cia[q] = g_ci[MM + j];  cib[q] = j ? g_ci[j - 1] : 0.f;
        etm[q] = g_et[j];       eti[q] = g_et[MM + j];
    }
    float et_x = 0.f, ci_xa = 0.f, ci_xb = 0.f;
    if (lastT) { et_x = g_et[KK - 1]; ci_xa = g_ci[KK - 1]; ci_xb = g_ci[MM - 1]; }
    __syncthreads();

    // init: u0 = exp(init) * emission(t=0)
    int cur = 0;
    {
        const float* ob = g_eobs + s_let[0] * KK;
        #pragma unroll
        for (int q = 0; q < 3; q++) {
            const int j = j0 + q;
            s_ea[0][j]      = g_einit[j]      * ob[j];
            s_ea[0][MM + j] = g_einit[MM + j] * ob[MM + j];
        }
        if (lastT) s_ea[0][KK - 1] = g_einit[KK - 1] * ob[KK - 1];
    }
    __syncthreads();

    int pacc = 0;

    for (int t = 1; t < LL; t++) {
        const float* u = s_ea[cur];
        const float* ob = g_eobs + s_let[t] * KK;   // L1-resident emission row
        float em[3], ei[3], ua[3], ub[3];
        #pragma unroll
        for (int q = 0; q < 3; q++) {
            const int j = j0 + q;
            ua[q] = u[MM + j];
            ub[q] = j ? u[j - 1] : 0.f;
            em[q] = ob[j];
            ei[q] = ob[MM + j];
        }
        float e_x = 0.f, u_x = 0.f, u_p = 0.f;
        if (lastT) { e_x = ob[KK - 1]; u_x = u[KK - 1]; u_p = u[MM - 1]; }

        // ---- phase 1: sources, serial 3-compose, 4-warp scan, z partial ----
        float Sr[3], zs = 0.f;
        #pragma unroll
        for (int q = 0; q < 3; q++) {
            Sr[q] = fmaf(ub[q], cfb[q], ua[q] * cfa[q]);
            zs += ua[q] + ub[q];
        }
        if (tid == 0) zs += u[MM - 1] + u[KK - 1];

        float Wv = w_[1], Sv = fmaf(w_[1], Sr[0], Sr[1]);   // compose elements 0,1
        Wv *= w_[0];
        Sv = fmaf(w_[2], Sv, Sr[2]); Wv *= w_[2];           // compose with 2

        #pragma unroll
        for (int o = 1; o < 32; o <<= 1) {
            float Wp = __shfl_up_sync(0xffffffffu, Wv, o);
            float Sp = __shfl_up_sync(0xffffffffu, Sv, o);
            if (lane >= o) { Sv = fmaf(Wv, Sp, Sv); Wv *= Wp; }
        }
        #pragma unroll
        for (int o = 16; o; o >>= 1) zs += __shfl_xor_sync(0xffffffffu, zs, o);
        if (lane == 31) s_T[wid] = make_float4(Wv, Sv, zs, 0.f);
        __syncthreads();

        // ---- phase 2: compose 4 warp totals (registers), combine 6 states ----
        const float4 T0 = s_T[0], T1 = s_T[1], T2 = s_T[2], T3 = s_T[3];
        const float Tz = ((T0.z + T1.z) + (T2.z + T3.z));
        float FinW = 0.f;
        if (wid > 0) FinW = T0.y;
        if (wid > 1) FinW = fmaf(T1.x, FinW, T1.y);
        if (wid > 2) FinW = fmaf(T2.x, FinW, T2.y);

        // power-of-two rescale from Z's exponent (exact, no MUFU)
        const unsigned ze = (__float_as_uint(Tz) >> 23) & 255u;
        pacc += (int)ze - 127;
        const float rz = __uint_as_float((254u - ze) << 23);

        // group-exclusive chain prefix via neighbor's inclusive registers
        const float Wp = __shfl_up_sync(0xffffffffu, Wv, 1);
        const float Sp = __shfl_up_sync(0xffffffffu, Sv, 1);
        float F0 = lane ? fmaf(Wp, FinW, Sp) : FinW;
        const float F1 = fmaf(w_[0], F0, Sr[0]);
        const float F2 = fmaf(w_[1], F1, Sr[1]);
        const float Fq[3] = {F0, F1, F2};

        float* un = s_ea[cur ^ 1];
        #pragma unroll
        for (int q = 0; q < 3; q++) {
            const int j = j0 + q;
            float prm = fmaf(ub[q], cmb[q], fmaf(ua[q], cma[q], etm[q] * Fq[q]));
            float pri = fmaf(ub[q], cib[q], fmaf(ua[q], cia[q], eti[q] * Fq[q]));
            un[j]      = prm * em[q] * rz;
            un[MM + j] = pri * ei[q] * rz;
        }
        if (lastT) {
            const float fmx = fmaf(Wv, FinW, Sv);   // global inclusive at element 383
            float prx = fmaf(u_p, ci_xb, fmaf(u_x, ci_xa, et_x * fmx));
            un[KK - 1] = prx * e_x * rz;
        }
        __syncthreads();
        cur ^= 1;
    }

    // ---- final: log(sum u) + 2^pacc correction ----
    const float* u = s_ea[cur];
    float ps = 0.f;
    #pragma unroll
    for (int q = 0; q < 3; q++) ps += u[j0 + q] + u[MM + j0 + q];
    if (lastT) ps += u[KK - 1];
    #pragma unroll
    for (int o = 16; o; o >>= 1) ps += __shfl_xor_sync(0xffffffffu, ps, o);
    if (lane == 0) s_red[wid] = ps;
    __syncthreads();
    if (tid == 0) {
        float Zt = ((s_red[0] + s_red[1]) + (s_red[2] + s_red[3]));
        out[b] = lscale[0] * ((float)((double)pacc * 0.6931471805599453) + __logf(Zt));
    }
}

extern "C" void kernel_launch(void* const* d_in, const int* in_sizes, int n_in,
                              void* d_out, int out_size)
{
    const float* pre  = (const float*)d_in[0];   // precursor_seq (384,21)
    const float* iseq = (const float*)d_in[1];   // insert_seq (385,21)
    const float* ins  = (const float*)d_in[2];   // insert (384,3,2)
    const float* del  = (const float*)d_in[3];   // delete (384,3,2)
    const float* seq  = (const float*)d_in[4];   // seq_data (64,256,21)
    const float* ls   = (const float*)d_in[5];   // local_scale (1,)
    float* out = (float*)d_out;                  // (64,)

    prep_kernel<<<1, 512>>>(pre, iseq, ins, del);
    hmm_forward<<<BB, 128>>>(seq, ls, out);
}